// round 6
// baseline (speedup 1.0000x reference)
#include <cuda_runtime.h>
#include <stdint.h>

#define BB 4
#define CC 256
#define DQK 32
#define NN 4096   // H*W
#define KT 32     // keys per tile
#define NKT (NN / KT)   // 128

#define QSTR 68
#define KSTR 36
#define VSTR 264
#define PSTR 36

__device__ float g_q[BB * NN * DQK];     // [b][n][d]
__device__ float g_k[BB * NN * DQK];     // [b][m][d]
__device__ float g_v[BB * NN * CC];      // [b][m][c]

__device__ __forceinline__ uint32_t f2tf32(float f) {
    uint32_t u;
    asm("cvt.rna.tf32.f32 %0, %1;" : "=r"(u) : "f"(f));
    return u;
}

__device__ __forceinline__ void mma_tf32(float d[4],
    uint32_t a0, uint32_t a1, uint32_t a2, uint32_t a3,
    uint32_t b0, uint32_t b1)
{
    asm volatile(
        "mma.sync.aligned.m16n8k8.row.col.f32.tf32.tf32.f32 "
        "{%0,%1,%2,%3},{%4,%5,%6,%7},{%8,%9},{%0,%1,%2,%3};"
        : "+f"(d[0]), "+f"(d[1]), "+f"(d[2]), "+f"(d[3])
        : "r"(a0), "r"(a1), "r"(a2), "r"(a3), "r"(b0), "r"(b1));
}

// ---------------------------------------------------------------------------
// Projection (unchanged): out[(b*N+n)*dout + j] = bias[j] + sum_c W[j][c] X[b][c][n]
// ---------------------------------------------------------------------------
__global__ __launch_bounds__(256) void proj_kernel(
    const float* __restrict__ X, const float* __restrict__ W,
    const float* __restrict__ bias, float* __restrict__ out, int dout)
{
    const int b  = blockIdx.z;
    const int n0 = blockIdx.x * 128;
    const int j0 = blockIdx.y * 32;
    const int t  = threadIdx.x;
    const int tx = t & 31;
    const int ty = t >> 5;

    __shared__ float As[32][128];
    __shared__ float Bs[32][32];

    float acc[4][4];
#pragma unroll
    for (int i = 0; i < 4; i++)
#pragma unroll
        for (int u = 0; u < 4; u++) acc[i][u] = 0.f;

    const float* Xb = X + b * CC * NN;

    for (int c0 = 0; c0 < CC; c0 += 32) {
#pragma unroll
        for (int i = 0; i < 4; i++) {
            int idx = t + 256 * i;
            int cc  = idx >> 5;
            int nn  = (idx & 31) * 4;
            float4 v = *(const float4*)(Xb + (c0 + cc) * NN + n0 + nn);
            *(float4*)&As[cc][nn] = v;
        }
        {
            int jj = t >> 3;
            int c4 = (t & 7) * 4;
            float4 wv = *(const float4*)(W + (j0 + jj) * CC + c0 + c4);
            *(float4*)&Bs[jj][c4] = wv;
        }
        __syncthreads();

#pragma unroll
        for (int cc = 0; cc < 32; cc++) {
            float4 a = *(const float4*)&As[cc][tx * 4];
            float b0 = Bs[ty * 4 + 0][cc];
            float b1 = Bs[ty * 4 + 1][cc];
            float b2 = Bs[ty * 4 + 2][cc];
            float b3 = Bs[ty * 4 + 3][cc];
            acc[0][0] += a.x * b0; acc[0][1] += a.x * b1; acc[0][2] += a.x * b2; acc[0][3] += a.x * b3;
            acc[1][0] += a.y * b0; acc[1][1] += a.y * b1; acc[1][2] += a.y * b2; acc[1][3] += a.y * b3;
            acc[2][0] += a.z * b0; acc[2][1] += a.z * b1; acc[2][2] += a.z * b2; acc[2][3] += a.z * b3;
            acc[3][0] += a.w * b0; acc[3][1] += a.w * b1; acc[3][2] += a.w * b2; acc[3][3] += a.w * b3;
        }
        __syncthreads();
    }

    float bj0 = bias[j0 + ty * 4 + 0];
    float bj1 = bias[j0 + ty * 4 + 1];
    float bj2 = bias[j0 + ty * 4 + 2];
    float bj3 = bias[j0 + ty * 4 + 3];
#pragma unroll
    for (int i = 0; i < 4; i++) {
        float4 r;
        r.x = acc[i][0] + bj0;
        r.y = acc[i][1] + bj1;
        r.z = acc[i][2] + bj2;
        r.w = acc[i][3] + bj3;
        int n = n0 + tx * 4 + i;
        *(float4*)(out + (b * NN + n) * dout + j0 + ty * 4) = r;
    }
}

// ---------------------------------------------------------------------------
// Pipelined flash attention. 64 queries/CTA, 256 threads, 32-key ktiles,
// double-buffered K/V/P. Region A (read-only): PV-mma[k] || S-FFMA[k+1].
// Region B (writes): exp->P[k+1], V[k+1] STS, K[k+2] STS.
// ---------------------------------------------------------------------------
__device__ __forceinline__ void load_k_tile(const float* __restrict__ gk_b,
                                            int mb, float* Kt, int t)
{
    int m  = t >> 3;                    // 0..31
    int d4 = (t & 7) * 4;
    float4 v = *(const float4*)(gk_b + (mb + m) * DQK + d4);
    Kt[(d4 + 0) * KSTR + m] = v.x;
    Kt[(d4 + 1) * KSTR + m] = v.y;
    Kt[(d4 + 2) * KSTR + m] = v.z;
    Kt[(d4 + 3) * KSTR + m] = v.w;
}

__device__ __forceinline__ void load_v_tile(const float* __restrict__ gv_b,
                                            int mb, uint32_t* Vs, int t)
{
#pragma unroll
    for (int i = 0; i < 8; i++) {
        int idx = t + 256 * i;
        int m   = idx >> 6;             // 0..31
        int c4  = (idx & 63) * 4;
        float4 v = *(const float4*)(gv_b + (mb + m) * CC + c4);
        uint4 u;
        u.x = f2tf32(v.x); u.y = f2tf32(v.y);
        u.z = f2tf32(v.z); u.w = f2tf32(v.w);
        *(uint4*)&Vs[m * VSTR + c4] = u;
    }
}

__device__ __forceinline__ void compute_s(const float* Qt, const float* Kt,
                                          int rS, int mS, float s[4][2])
{
#pragma unroll
    for (int i = 0; i < 4; i++) { s[i][0] = 0.f; s[i][1] = 0.f; }
#pragma unroll
    for (int d = 0; d < DQK; d++) {
        float4 q4 = *(const float4*)&Qt[d * QSTR + rS];
        float2 k2 = *(const float2*)&Kt[d * KSTR + mS];
        s[0][0] += q4.x * k2.x; s[0][1] += q4.x * k2.y;
        s[1][0] += q4.y * k2.x; s[1][1] += q4.y * k2.y;
        s[2][0] += q4.z * k2.x; s[2][1] += q4.z * k2.y;
        s[3][0] += q4.w * k2.x; s[3][1] += q4.w * k2.y;
    }
}

__device__ __forceinline__ void exp_store(const float s[4][2], float* lrun,
                                          uint32_t* Ps, int rS, int mS)
{
#pragma unroll
    for (int i = 0; i < 4; i++) {
        float e0 = __expf(s[i][0]);
        float e1 = __expf(s[i][1]);
        lrun[i] += e0 + e1;
        uint2 u;
        u.x = f2tf32(e0); u.y = f2tf32(e1);
        *(uint2*)&Ps[(rS + i) * PSTR + mS] = u;
    }
}

__device__ __forceinline__ void pv_mma(const uint32_t* Ps, const uint32_t* Vs,
                                       float acc[4][4][4],
                                       int gid, int tid, int cbase)
{
#pragma unroll
    for (int ks = 0; ks < 4; ks++) {
        const int m0 = ks * 8;
        uint32_t b0[4], b1[4];
#pragma unroll
        for (int jt = 0; jt < 4; jt++) {
            b0[jt] = Vs[(m0 + tid)     * VSTR + cbase + jt * 8 + gid];
            b1[jt] = Vs[(m0 + tid + 4) * VSTR + cbase + jt * 8 + gid];
        }
#pragma unroll
        for (int it = 0; it < 4; it++) {
            uint32_t a0 = Ps[(it * 16 + gid)     * PSTR + m0 + tid];
            uint32_t a1 = Ps[(it * 16 + gid + 8) * PSTR + m0 + tid];
            uint32_t a2 = Ps[(it * 16 + gid)     * PSTR + m0 + tid + 4];
            uint32_t a3 = Ps[(it * 16 + gid + 8) * PSTR + m0 + tid + 4];
#pragma unroll
            for (int jt = 0; jt < 4; jt++)
                mma_tf32(acc[it][jt], a0, a1, a2, a3, b0[jt], b1[jt]);
        }
    }
}

#define SMEM_FLOATS (32*QSTR + 2*32*KSTR + 2*32*VSTR + 2*64*PSTR + 64)

__global__ __launch_bounds__(256, 2) void flash_kernel(float* __restrict__ out)
{
    extern __shared__ float sm[];
    float*    Qt   = sm;                               // 32*68
    float*    Kt0  = Qt  + 32 * QSTR;                  // 32*36
    float*    Kt1  = Kt0 + 32 * KSTR;
    uint32_t* Vs0  = (uint32_t*)(Kt1 + 32 * KSTR);     // 32*264
    uint32_t* Vs1  = Vs0 + 32 * VSTR;
    uint32_t* Ps0  = Vs1 + 32 * VSTR;                  // 64*36
    uint32_t* Ps1  = Ps0 + 64 * PSTR;
    float*    inv_s = (float*)(Ps1 + 64 * PSTR);       // 64

    const int b    = blockIdx.y;
    const int n0   = blockIdx.x * 64;
    const int t    = threadIdx.x;
    const int rS   = (t >> 4) * 4;
    const int mS   = (t & 15) * 2;
    const int lane  = t & 31;
    const int gid   = lane >> 2;
    const int tid   = lane & 3;
    const int cbase = (t >> 5) * 32;

    const float* gq_b = g_q + (size_t)b * NN * DQK;
    const float* gk_b = g_k + (size_t)b * NN * DQK;
    const float* gv_b = g_v + (size_t)b * NN * CC;

    // Load Q transposed: Qt[d][r]
#pragma unroll
    for (int i = 0; i < 2; i++) {
        int idx = t + 256 * i;
        int qr  = idx >> 3;
        int d4  = (idx & 7) * 4;
        float4 v = *(const float4*)(gq_b + (n0 + qr) * DQK + d4);
        Qt[(d4 + 0) * QSTR + qr] = v.x;
        Qt[(d4 + 1) * QSTR + qr] = v.y;
        Qt[(d4 + 2) * QSTR + qr] = v.z;
        Qt[(d4 + 3) * QSTR + qr] = v.w;
    }

    float acc[4][4][4];
#pragma unroll
    for (int it = 0; it < 4; it++)
#pragma unroll
        for (int jt = 0; jt < 4; jt++)
#pragma unroll
            for (int u = 0; u < 4; u++) acc[it][jt][u] = 0.f;

    float lrun[4] = {0.f, 0.f, 0.f, 0.f};
    float s[4][2];

    // Prologue: tile 0 into buf0, P[0], K[1] into buf1
    load_k_tile(gk_b, 0, Kt0, t);
    load_v_tile(gv_b, 0, Vs0, t);
    __syncthreads();
    compute_s(Qt, Kt0, rS, mS, s);
    exp_store(s, lrun, Ps0, rS, mS);
    load_k_tile(gk_b, KT, Kt1, t);
    __syncthreads();

    // Steady state: iterations k = 0 .. 126 (pairs + one tail)
#define PIPE_BODY(K, PC, VC, KN, PN, VN, KW, DO_K)                         \
    do {                                                                    \
        pv_mma(PC, VC, acc, gid, tid, cbase);                               \
        compute_s(Qt, KN, rS, mS, s);                                       \
        __syncthreads();                                                    \
        exp_store(s, lrun, PN, rS, mS);                                     \
        load_v_tile(gv_b, ((K) + 1) * KT, VN, t);                           \
        if (DO_K) load_k_tile(gk_b, ((K) + 2) * KT, KW, t);                 \
        __syncthreads();                                                    \
    } while (0)

    for (int k = 0; k < NKT - 2; k += 2) {
        PIPE_BODY(k,     Ps0, Vs0, Kt1, Ps1, Vs1, Kt0, true);
        PIPE_BODY(k + 1, Ps1, Vs1, Kt0, Ps0, Vs0, Kt1, (k + 1 < NKT - 2));
    }
    // k = 126 (NKT-2): PV tile126 (buf0), S tile127 (Kt1), store P127/V127 (buf1)
    PIPE_BODY(NKT - 2, Ps0, Vs0, Kt1, Ps1, Vs1, Kt0, false);
    // Final PV: tile 127 (buf1)
    pv_mma(Ps1, Vs1, acc, gid, tid, cbase);

    // Row-sum reduction (once)
#pragma unroll
    for (int i = 0; i < 4; i++) {
        float l = lrun[i];
        l += __shfl_xor_sync(0xffffffffu, l, 1);
        l += __shfl_xor_sync(0xffffffffu, l, 2);
        l += __shfl_xor_sync(0xffffffffu, l, 4);
        l += __shfl_xor_sync(0xffffffffu, l, 8);
        if ((t & 15) == 0) inv_s[rS + i] = 1.f / l;
    }
    __syncthreads();   // also guards Vs reads (final PV) before staging below

    // Stage normalized O into smem (reuse Vs0..Vs1 as 64 x VSTR scratch)
    float* Stage = (float*)Vs0;
#pragma unroll
    for (int it = 0; it < 4; it++) {
        int r_lo = it * 16 + gid;
        int r_hi = r_lo + 8;
        float ilo = inv_s[r_lo];
        float ihi = inv_s[r_hi];
#pragma unroll
        for (int jt = 0; jt < 4; jt++) {
            float2 lo, hi;
            lo.x = acc[it][jt][0] * ilo; lo.y = acc[it][jt][1] * ilo;
            hi.x = acc[it][jt][2] * ihi; hi.y = acc[it][jt][3] * ihi;
            *(float2*)&Stage[r_lo * VSTR + cbase + jt * 8 + tid * 2] = lo;
            *(float2*)&Stage[r_hi * VSTR + cbase + jt * 8 + tid * 2] = hi;
        }
    }
    __syncthreads();

    // Transposed write: out[b][c][n0..n0+63]
    const int c = t;
    float* ob = out + ((size_t)b * CC + c) * NN + n0;
#pragma unroll
    for (int i = 0; i < 16; i++) {
        float4 v;
        v.x = Stage[(4 * i + 0) * VSTR + c];
        v.y = Stage[(4 * i + 1) * VSTR + c];
        v.z = Stage[(4 * i + 2) * VSTR + c];
        v.w = Stage[(4 * i + 3) * VSTR + c];
        *(float4*)(ob + 4 * i) = v;
    }
}

// ---------------------------------------------------------------------------
extern "C" void kernel_launch(void* const* d_in, const int* in_sizes, int n_in,
                              void* d_out, int out_size)
{
    const float* f1 = (const float*)d_in[0];
    const float* f2 = (const float*)d_in[1];
    const float* Wq = (const float*)d_in[2];
    const float* bq = (const float*)d_in[3];
    const float* Wk = (const float*)d_in[4];
    const float* bk = (const float*)d_in[5];
    const float* Wv = (const float*)d_in[6];
    const float* bv = (const float*)d_in[7];
    float* out = (float*)d_out;

    float *qp, *kp, *vp;
    cudaGetSymbolAddress((void**)&qp, g_q);
    cudaGetSymbolAddress((void**)&kp, g_k);
    cudaGetSymbolAddress((void**)&vp, g_v);

    const int smem_bytes = SMEM_FLOATS * (int)sizeof(float);
    cudaFuncSetAttribute(flash_kernel,
                         cudaFuncAttributeMaxDynamicSharedMemorySize, smem_bytes);

    proj_kernel<<<dim3(NN / 128, 1, BB), 256>>>(f1, Wq, bq, qp, DQK);
    proj_kernel<<<dim3(NN / 128, 1, BB), 256>>>(f2, Wk, bk, kp, DQK);
    proj_kernel<<<dim3(NN / 128, 8, BB), 256>>>(f2, Wv, bv, vp, CC);
    flash_kernel<<<dim3(NN / 64, BB), 256, smem_bytes>>>(out);
}

// round 7
// speedup vs baseline: 1.0471x; 1.0471x over previous
#include <cuda_runtime.h>
#include <stdint.h>

#define BB 4
#define CC 256
#define DQK 32
#define NN 4096   // H*W
#define KT 64     // keys per tile
#define NKT (NN / KT)   // 64

#define TSTR 68   // Qt/Kt/Ps smem stride

__device__ float g_q[BB * NN * DQK];     // [b][n][d]
__device__ float g_k[BB * NN * DQK];     // [b][m][d]
__device__ float g_v[BB * NN * CC];      // [b][m][c]

__device__ __forceinline__ uint32_t f2tf32(float f) {
    uint32_t u;
    asm("cvt.rna.tf32.f32 %0, %1;" : "=r"(u) : "f"(f));
    return u;
}

__device__ __forceinline__ void mma_tf32(float d[4],
    uint32_t a0, uint32_t a1, uint32_t a2, uint32_t a3,
    uint32_t b0, uint32_t b1)
{
    asm volatile(
        "mma.sync.aligned.m16n8k8.row.col.f32.tf32.tf32.f32 "
        "{%0,%1,%2,%3},{%4,%5,%6,%7},{%8,%9},{%0,%1,%2,%3};"
        : "+f"(d[0]), "+f"(d[1]), "+f"(d[2]), "+f"(d[3])
        : "r"(a0), "r"(a1), "r"(a2), "r"(a3), "r"(b0), "r"(b1));
}

// ---------------------------------------------------------------------------
// Projection: out[(b*N+n)*dout + j] = bias[j] + sum_c W[j][c] * X[b][c][n]
// ---------------------------------------------------------------------------
__global__ __launch_bounds__(256) void proj_kernel(
    const float* __restrict__ X, const float* __restrict__ W,
    const float* __restrict__ bias, float* __restrict__ out, int dout)
{
    const int b  = blockIdx.z;
    const int n0 = blockIdx.x * 128;
    const int j0 = blockIdx.y * 32;
    const int t  = threadIdx.x;
    const int tx = t & 31;
    const int ty = t >> 5;

    __shared__ float As[32][128];
    __shared__ float Bs[32][32];

    float acc[4][4];
#pragma unroll
    for (int i = 0; i < 4; i++)
#pragma unroll
        for (int u = 0; u < 4; u++) acc[i][u] = 0.f;

    const float* Xb = X + b * CC * NN;

    for (int c0 = 0; c0 < CC; c0 += 32) {
#pragma unroll
        for (int i = 0; i < 4; i++) {
            int idx = t + 256 * i;
            int cc  = idx >> 5;
            int nn  = (idx & 31) * 4;
            float4 v = *(const float4*)(Xb + (c0 + cc) * NN + n0 + nn);
            *(float4*)&As[cc][nn] = v;
        }
        {
            int jj = t >> 3;
            int c4 = (t & 7) * 4;
            float4 wv = *(const float4*)(W + (j0 + jj) * CC + c0 + c4);
            *(float4*)&Bs[jj][c4] = wv;
        }
        __syncthreads();

#pragma unroll
        for (int cc = 0; cc < 32; cc++) {
            float4 a = *(const float4*)&As[cc][tx * 4];
            float b0 = Bs[ty * 4 + 0][cc];
            float b1 = Bs[ty * 4 + 1][cc];
            float b2 = Bs[ty * 4 + 2][cc];
            float b3 = Bs[ty * 4 + 3][cc];
            acc[0][0] += a.x * b0; acc[0][1] += a.x * b1; acc[0][2] += a.x * b2; acc[0][3] += a.x * b3;
            acc[1][0] += a.y * b0; acc[1][1] += a.y * b1; acc[1][2] += a.y * b2; acc[1][3] += a.y * b3;
            acc[2][0] += a.z * b0; acc[2][1] += a.z * b1; acc[2][2] += a.z * b2; acc[2][3] += a.z * b3;
            acc[3][0] += a.w * b0; acc[3][1] += a.w * b1; acc[3][2] += a.w * b2; acc[3][3] += a.w * b3;
        }
        __syncthreads();
    }

    float bj0 = bias[j0 + ty * 4 + 0];
    float bj1 = bias[j0 + ty * 4 + 1];
    float bj2 = bias[j0 + ty * 4 + 2];
    float bj3 = bias[j0 + ty * 4 + 3];
#pragma unroll
    for (int i = 0; i < 4; i++) {
        float4 r;
        r.x = acc[i][0] + bj0;
        r.y = acc[i][1] + bj1;
        r.z = acc[i][2] + bj2;
        r.w = acc[i][3] + bj3;
        int n = n0 + tx * 4 + i;
        *(float4*)(out + (b * NN + n) * dout + j0 + ty * 4) = r;
    }
}

// ---------------------------------------------------------------------------
// Fused flash attention (R5 structure, V direct from gmem):
//   S = QK^T fp32 FFMA (4x4 tile/thread), P = exp(S) unnormalized,
//   PV via mma.tf32 with B-fragments LDG'd straight from g_v (no V smem),
//   K tile register-prefetched under the mma block. Direct STG epilogue.
// smem: Qt[32][68] Kt[32][68] Ps[64][68] inv[64]   (~35 KB)
// ---------------------------------------------------------------------------
#define SMEM_FLOATS (32*TSTR + 32*TSTR + 64*TSTR + 64)

__global__ __launch_bounds__(256, 2) void flash_kernel(float* __restrict__ out)
{
    extern __shared__ float sm[];
    float*    Qt    = sm;                    // [d][r]
    float*    Kt    = Qt + 32 * TSTR;        // [d][m]
    uint32_t* Ps    = (uint32_t*)(Kt + 32 * TSTR);   // [r][m] tf32 bits
    float*    inv_s = (float*)(Ps + 64 * TSTR);      // [r]

    const int b    = blockIdx.y;
    const int n0   = blockIdx.x * 64;
    const int t    = threadIdx.x;
    // S-phase mapping
    const int txS  = t & 15;
    const int rS   = (t >> 4) * 4;
    const int mS   = txS * 4;
    // PV (mma) mapping
    const int lane  = t & 31;
    const int gid   = lane >> 2;
    const int tid   = lane & 3;
    const int cbase = (t >> 5) * 32;

    const float* gq_b = g_q + (size_t)b * NN * DQK;
    const float* gk_b = g_k + (size_t)b * NN * DQK;
    const float* gv_b = g_v + (size_t)b * NN * CC;

    // K-load indexing (2 float4 per thread per tile)
    const int km0 = t >> 3;              // 0..31
    const int km1 = (t + 256) >> 3;      // 32..63
    const int kd4 = (t & 7) * 4;

    // Load Q transposed: Qt[d][r]
#pragma unroll
    for (int i = 0; i < 2; i++) {
        int idx = t + 256 * i;
        int qr  = idx >> 3;
        int d4  = (idx & 7) * 4;
        float4 v = *(const float4*)(gq_b + (n0 + qr) * DQK + d4);
        Qt[(d4 + 0) * TSTR + qr] = v.x;
        Qt[(d4 + 1) * TSTR + qr] = v.y;
        Qt[(d4 + 2) * TSTR + qr] = v.z;
        Qt[(d4 + 3) * TSTR + qr] = v.w;
    }

    float acc[4][4][4];
#pragma unroll
    for (int it = 0; it < 4; it++)
#pragma unroll
        for (int jt = 0; jt < 4; jt++)
#pragma unroll
            for (int u = 0; u < 4; u++) acc[it][jt][u] = 0.f;

    float lrun[4] = {0.f, 0.f, 0.f, 0.f};

    // Prologue: K(0) into smem, S(0) -> P(0)
    {
        float4 ka = *(const float4*)(gk_b + km0 * DQK + kd4);
        float4 kb = *(const float4*)(gk_b + km1 * DQK + kd4);
        Kt[(kd4 + 0) * TSTR + km0] = ka.x;
        Kt[(kd4 + 1) * TSTR + km0] = ka.y;
        Kt[(kd4 + 2) * TSTR + km0] = ka.z;
        Kt[(kd4 + 3) * TSTR + km0] = ka.w;
        Kt[(kd4 + 0) * TSTR + km1] = kb.x;
        Kt[(kd4 + 1) * TSTR + km1] = kb.y;
        Kt[(kd4 + 2) * TSTR + km1] = kb.z;
        Kt[(kd4 + 3) * TSTR + km1] = kb.w;
    }
    __syncthreads();

    // S(0) + exp + P store
    {
        float s[4][4];
#pragma unroll
        for (int i = 0; i < 4; i++)
#pragma unroll
            for (int j = 0; j < 4; j++) s[i][j] = 0.f;
#pragma unroll
        for (int d = 0; d < DQK; d++) {
            float4 q4 = *(const float4*)&Qt[d * TSTR + rS];
            float4 k4 = *(const float4*)&Kt[d * TSTR + mS];
            s[0][0] += q4.x * k4.x; s[0][1] += q4.x * k4.y; s[0][2] += q4.x * k4.z; s[0][3] += q4.x * k4.w;
            s[1][0] += q4.y * k4.x; s[1][1] += q4.y * k4.y; s[1][2] += q4.y * k4.z; s[1][3] += q4.y * k4.w;
            s[2][0] += q4.z * k4.x; s[2][1] += q4.z * k4.y; s[2][2] += q4.z * k4.z; s[2][3] += q4.z * k4.w;
            s[3][0] += q4.w * k4.x; s[3][1] += q4.w * k4.y; s[3][2] += q4.w * k4.z; s[3][3] += q4.w * k4.w;
        }
#pragma unroll
        for (int i = 0; i < 4; i++) {
            float e0 = __expf(s[i][0]);
            float e1 = __expf(s[i][1]);
            float e2 = __expf(s[i][2]);
            float e3 = __expf(s[i][3]);
            lrun[i] += (e0 + e1) + (e2 + e3);
            uint4 pu;
            pu.x = f2tf32(e0); pu.y = f2tf32(e1);
            pu.z = f2tf32(e2); pu.w = f2tf32(e3);
            *(uint4*)&Ps[(rS + i) * TSTR + mS] = pu;
        }
    }
    __syncthreads();

    for (int kt = 0; kt < NKT; kt++) {
        const bool more = (kt + 1 < NKT);

        // Prefetch K(kt+1) into registers (hidden under the mma block)
        float4 ka, kb;
        if (more) {
            const float* gk_t = gk_b + (kt + 1) * KT * DQK;
            ka = *(const float4*)(gk_t + km0 * DQK + kd4);
            kb = *(const float4*)(gk_t + km1 * DQK + kd4);
        }

        // --- PV: O += P V, B-fragments straight from gmem ---
        {
            const float* vb = gv_b + (size_t)(kt * KT) * CC + tid * CC + cbase + gid;
#pragma unroll
            for (int ks = 0; ks < 8; ks++) {
                const int m0 = ks * 8;
                uint32_t b0[4], b1[4];
#pragma unroll
                for (int jt = 0; jt < 4; jt++) {
                    b0[jt] = f2tf32(vb[(m0    ) * CC + jt * 8]);
                    b1[jt] = f2tf32(vb[(m0 + 4) * CC + jt * 8]);
                }
#pragma unroll
                for (int it = 0; it < 4; it++) {
                    uint32_t a0 = Ps[(it * 16 + gid)     * TSTR + m0 + tid];
                    uint32_t a1 = Ps[(it * 16 + gid + 8) * TSTR + m0 + tid];
                    uint32_t a2 = Ps[(it * 16 + gid)     * TSTR + m0 + tid + 4];
                    uint32_t a3 = Ps[(it * 16 + gid + 8) * TSTR + m0 + tid + 4];
#pragma unroll
                    for (int jt = 0; jt < 4; jt++)
                        mma_tf32(acc[it][jt], a0, a1, a2, a3, b0[jt], b1[jt]);
                }
            }
        }

        // Stage K(kt+1) into smem
        if (more) {
            Kt[(kd4 + 0) * TSTR + km0] = ka.x;
            Kt[(kd4 + 1) * TSTR + km0] = ka.y;
            Kt[(kd4 + 2) * TSTR + km0] = ka.z;
            Kt[(kd4 + 3) * TSTR + km0] = ka.w;
            Kt[(kd4 + 0) * TSTR + km1] = kb.x;
            Kt[(kd4 + 1) * TSTR + km1] = kb.y;
            Kt[(kd4 + 2) * TSTR + km1] = kb.z;
            Kt[(kd4 + 3) * TSTR + km1] = kb.w;
        }
        __syncthreads();

        // --- S(kt+1) + exp + P store ---
        if (more) {
            float s[4][4];
#pragma unroll
            for (int i = 0; i < 4; i++)
#pragma unroll
                for (int j = 0; j < 4; j++) s[i][j] = 0.f;
#pragma unroll
            for (int d = 0; d < DQK; d++) {
                float4 q4 = *(const float4*)&Qt[d * TSTR + rS];
                float4 k4 = *(const float4*)&Kt[d * TSTR + mS];
                s[0][0] += q4.x * k4.x; s[0][1] += q4.x * k4.y; s[0][2] += q4.x * k4.z; s[0][3] += q4.x * k4.w;
                s[1][0] += q4.y * k4.x; s[1][1] += q4.y * k4.y; s[1][2] += q4.y * k4.z; s[1][3] += q4.y * k4.w;
                s[2][0] += q4.z * k4.x; s[2][1] += q4.z * k4.y; s[2][2] += q4.z * k4.z; s[2][3] += q4.z * k4.w;
                s[3][0] += q4.w * k4.x; s[3][1] += q4.w * k4.y; s[3][2] += q4.w * k4.z; s[3][3] += q4.w * k4.w;
            }
#pragma unroll
            for (int i = 0; i < 4; i++) {
                float e0 = __expf(s[i][0]);
                float e1 = __expf(s[i][1]);
                float e2 = __expf(s[i][2]);
                float e3 = __expf(s[i][3]);
                lrun[i] += (e0 + e1) + (e2 + e3);
                uint4 pu;
                pu.x = f2tf32(e0); pu.y = f2tf32(e1);
                pu.z = f2tf32(e2); pu.w = f2tf32(e3);
                *(uint4*)&Ps[(rS + i) * TSTR + mS] = pu;
            }
        }
        __syncthreads();
    }

    // --- final row-sum reduction ---
#pragma unroll
    for (int i = 0; i < 4; i++) {
        float l = lrun[i];
        l += __shfl_xor_sync(0xffffffffu, l, 1);
        l += __shfl_xor_sync(0xffffffffu, l, 2);
        l += __shfl_xor_sync(0xffffffffu, l, 4);
        l += __shfl_xor_sync(0xffffffffu, l, 8);
        if (txS == 0) inv_s[rS + i] = 1.f / l;
    }
    __syncthreads();

    // --- direct STG epilogue: out[b][c][n0+r] ---
    float* ob = out + (size_t)b * CC * NN + n0;
#pragma unroll
    for (int it = 0; it < 4; it++) {
        const int r_lo = it * 16 + gid;
        const int r_hi = r_lo + 8;
        const float ilo = inv_s[r_lo];
        const float ihi = inv_s[r_hi];
#pragma unroll
        for (int jt = 0; jt < 4; jt++) {
            const int c0 = cbase + jt * 8 + tid * 2;
            ob[(size_t)(c0    ) * NN + r_lo] = acc[it][jt][0] * ilo;
            ob[(size_t)(c0 + 1) * NN + r_lo] = acc[it][jt][1] * ilo;
            ob[(size_t)(c0    ) * NN + r_hi] = acc[it][jt][2] * ihi;
            ob[(size_t)(c0 + 1) * NN + r_hi] = acc[it][jt][3] * ihi;
        }
    }
}

// ---------------------------------------------------------------------------
extern "C" void kernel_launch(void* const* d_in, const int* in_sizes, int n_in,
                              void* d_out, int out_size)
{
    const float* f1 = (const float*)d_in[0];
    const float* f2 = (const float*)d_in[1];
    const float* Wq = (const float*)d_in[2];
    const float* bq = (const float*)d_in[3];
    const float* Wk = (const float*)d_in[4];
    const float* bk = (const float*)d_in[5];
    const float* Wv = (const float*)d_in[6];
    const float* bv = (const float*)d_in[7];
    float* out = (float*)d_out;

    float *qp, *kp, *vp;
    cudaGetSymbolAddress((void**)&qp, g_q);
    cudaGetSymbolAddress((void**)&kp, g_k);
    cudaGetSymbolAddress((void**)&vp, g_v);

    const int smem_bytes = SMEM_FLOATS * (int)sizeof(float);
    cudaFuncSetAttribute(flash_kernel,
                         cudaFuncAttributeMaxDynamicSharedMemorySize, smem_bytes);

    proj_kernel<<<dim3(NN / 128, 1, BB), 256>>>(f1, Wq, bq, qp, DQK);
    proj_kernel<<<dim3(NN / 128, 1, BB), 256>>>(f2, Wk, bk, kp, DQK);
    proj_kernel<<<dim3(NN / 128, 8, BB), 256>>>(f2, Wv, bv, vp, CC);
    flash_kernel<<<dim3(NN / 64, BB), 256, smem_bytes>>>(out);
}

// round 8
// speedup vs baseline: 1.0500x; 1.0027x over previous
#include <cuda_runtime.h>
#include <stdint.h>

#define BB 4
#define CC 256
#define DQK 32
#define NN 4096   // H*W
#define KT 64     // keys per tile
#define NKT (NN / KT)   // 64

#define TSTR 68   // Qt/Kt/Ps smem stride

__device__ float g_q[BB * NN * DQK];     // [b][n][d]
__device__ float g_k[BB * NN * DQK];     // [b][m][d]
__device__ float g_v[BB * NN * CC];      // [b][m][c]

__device__ __forceinline__ uint32_t f2tf32(float f) {
    uint32_t u;
    asm("cvt.rna.tf32.f32 %0, %1;" : "=r"(u) : "f"(f));
    return u;
}

__device__ __forceinline__ void mma_tf32(float d[4],
    uint32_t a0, uint32_t a1, uint32_t a2, uint32_t a3,
    uint32_t b0, uint32_t b1)
{
    asm volatile(
        "mma.sync.aligned.m16n8k8.row.col.f32.tf32.tf32.f32 "
        "{%0,%1,%2,%3},{%4,%5,%6,%7},{%8,%9},{%0,%1,%2,%3};"
        : "+f"(d[0]), "+f"(d[1]), "+f"(d[2]), "+f"(d[3])
        : "r"(a0), "r"(a1), "r"(a2), "r"(a3), "r"(b0), "r"(b1));
}

// ---------------------------------------------------------------------------
// Projection: out[(b*N+n)*dout + j] = bias[j] + sum_c W[j][c] * X[b][c][n]
// ---------------------------------------------------------------------------
__global__ __launch_bounds__(256) void proj_kernel(
    const float* __restrict__ X, const float* __restrict__ W,
    const float* __restrict__ bias, float* __restrict__ out, int dout)
{
    const int b  = blockIdx.z;
    const int n0 = blockIdx.x * 128;
    const int j0 = blockIdx.y * 32;
    const int t  = threadIdx.x;
    const int tx = t & 31;
    const int ty = t >> 5;

    __shared__ float As[32][128];
    __shared__ float Bs[32][32];

    float acc[4][4];
#pragma unroll
    for (int i = 0; i < 4; i++)
#pragma unroll
        for (int u = 0; u < 4; u++) acc[i][u] = 0.f;

    const float* Xb = X + b * CC * NN;

    for (int c0 = 0; c0 < CC; c0 += 32) {
#pragma unroll
        for (int i = 0; i < 4; i++) {
            int idx = t + 256 * i;
            int cc  = idx >> 5;
            int nn  = (idx & 31) * 4;
            float4 v = *(const float4*)(Xb + (c0 + cc) * NN + n0 + nn);
            *(float4*)&As[cc][nn] = v;
        }
        {
            int jj = t >> 3;
            int c4 = (t & 7) * 4;
            float4 wv = *(const float4*)(W + (j0 + jj) * CC + c0 + c4);
            *(float4*)&Bs[jj][c4] = wv;
        }
        __syncthreads();

#pragma unroll
        for (int cc = 0; cc < 32; cc++) {
            float4 a = *(const float4*)&As[cc][tx * 4];
            float b0 = Bs[ty * 4 + 0][cc];
            float b1 = Bs[ty * 4 + 1][cc];
            float b2 = Bs[ty * 4 + 2][cc];
            float b3 = Bs[ty * 4 + 3][cc];
            acc[0][0] += a.x * b0; acc[0][1] += a.x * b1; acc[0][2] += a.x * b2; acc[0][3] += a.x * b3;
            acc[1][0] += a.y * b0; acc[1][1] += a.y * b1; acc[1][2] += a.y * b2; acc[1][3] += a.y * b3;
            acc[2][0] += a.z * b0; acc[2][1] += a.z * b1; acc[2][2] += a.z * b2; acc[2][3] += a.z * b3;
            acc[3][0] += a.w * b0; acc[3][1] += a.w * b1; acc[3][2] += a.w * b2; acc[3][3] += a.w * b3;
        }
        __syncthreads();
    }

    float bj0 = bias[j0 + ty * 4 + 0];
    float bj1 = bias[j0 + ty * 4 + 1];
    float bj2 = bias[j0 + ty * 4 + 2];
    float bj3 = bias[j0 + ty * 4 + 3];
#pragma unroll
    for (int i = 0; i < 4; i++) {
        float4 r;
        r.x = acc[i][0] + bj0;
        r.y = acc[i][1] + bj1;
        r.z = acc[i][2] + bj2;
        r.w = acc[i][3] + bj3;
        int n = n0 + tx * 4 + i;
        *(float4*)(out + (b * NN + n) * dout + j0 + ty * 4) = r;
    }
}

// ---------------------------------------------------------------------------
// Fused flash attention, single-sync pipeline:
//   iter k: [LDG K(k+2)] [STS K(k+2)->Kt[k%2]] PV(k){Ps[k%2], V prefetch}
//           S(k+1){Kt[(k+1)%2]} exp->Ps[(k+1)%2]  preload V0(k+1)  sync
// smem: Qt[32][68] Kt0/1[32][68] Ps0/1[64][68] inv[64]  (~60 KB)
// ---------------------------------------------------------------------------
#define SMEM_FLOATS (32*TSTR + 2*32*TSTR + 2*64*TSTR + 64)

__global__ __launch_bounds__(256, 2) void flash_kernel(float* __restrict__ out)
{
    extern __shared__ float sm[];
    float*    Qt    = sm;                       // [d][r]
    float*    Kt0   = Qt  + 32 * TSTR;          // [d][m]
    float*    Kt1   = Kt0 + 32 * TSTR;
    uint32_t* Ps0   = (uint32_t*)(Kt1 + 32 * TSTR);  // [r][m] tf32 bits
    uint32_t* Ps1   = Ps0 + 64 * TSTR;
    float*    inv_s = (float*)(Ps1 + 64 * TSTR);     // [r]

    const int b    = blockIdx.y;
    const int n0   = blockIdx.x * 64;
    const int t    = threadIdx.x;
    // S-phase mapping
    const int txS  = t & 15;
    const int rS   = (t >> 4) * 4;
    const int mS   = txS * 4;
    // PV (mma) mapping
    const int lane  = t & 31;
    const int gid   = lane >> 2;
    const int tid   = lane & 3;
    const int cbase = (t >> 5) * 32;

    const float* gq_b = g_q + (size_t)b * NN * DQK;
    const float* gk_b = g_k + (size_t)b * NN * DQK;
    const float* gv_b = g_v + (size_t)b * NN * CC;
    const float* gv_w = gv_b + tid * CC + cbase + gid;   // warp V base

    // K-load indexing (2 float4 per thread per tile)
    const int km0 = t >> 3;              // 0..31
    const int km1 = (t + 256) >> 3;      // 32..63
    const int kd4 = (t & 7) * 4;

    // Load Q transposed: Qt[d][r]
#pragma unroll
    for (int i = 0; i < 2; i++) {
        int idx = t + 256 * i;
        int qr  = idx >> 3;
        int d4  = (idx & 7) * 4;
        float4 v = *(const float4*)(gq_b + (n0 + qr) * DQK + d4);
        Qt[(d4 + 0) * TSTR + qr] = v.x;
        Qt[(d4 + 1) * TSTR + qr] = v.y;
        Qt[(d4 + 2) * TSTR + qr] = v.z;
        Qt[(d4 + 3) * TSTR + qr] = v.w;
    }

    float acc[4][4][4];
#pragma unroll
    for (int it = 0; it < 4; it++)
#pragma unroll
        for (int jt = 0; jt < 4; jt++)
#pragma unroll
            for (int u = 0; u < 4; u++) acc[it][jt][u] = 0.f;

    float lrun[4] = {0.f, 0.f, 0.f, 0.f};

    // --- helpers as lambdas (inlined) ---
    auto stage_k = [&](const float* gk_t, float* Kw) {
        float4 ka = *(const float4*)(gk_t + km0 * DQK + kd4);
        float4 kb = *(const float4*)(gk_t + km1 * DQK + kd4);
        Kw[(kd4 + 0) * TSTR + km0] = ka.x;
        Kw[(kd4 + 1) * TSTR + km0] = ka.y;
        Kw[(kd4 + 2) * TSTR + km0] = ka.z;
        Kw[(kd4 + 3) * TSTR + km0] = ka.w;
        Kw[(kd4 + 0) * TSTR + km1] = kb.x;
        Kw[(kd4 + 1) * TSTR + km1] = kb.y;
        Kw[(kd4 + 2) * TSTR + km1] = kb.z;
        Kw[(kd4 + 3) * TSTR + km1] = kb.w;
    };

    auto s_phase = [&](const float* Kc, uint32_t* Pw) {
        float s[4][4];
#pragma unroll
        for (int i = 0; i < 4; i++)
#pragma unroll
            for (int j = 0; j < 4; j++) s[i][j] = 0.f;
#pragma unroll
        for (int d = 0; d < DQK; d++) {
            float4 q4 = *(const float4*)&Qt[d * TSTR + rS];
            float4 k4 = *(const float4*)&Kc[d * TSTR + mS];
            s[0][0] += q4.x * k4.x; s[0][1] += q4.x * k4.y; s[0][2] += q4.x * k4.z; s[0][3] += q4.x * k4.w;
            s[1][0] += q4.y * k4.x; s[1][1] += q4.y * k4.y; s[1][2] += q4.y * k4.z; s[1][3] += q4.y * k4.w;
            s[2][0] += q4.z * k4.x; s[2][1] += q4.z * k4.y; s[2][2] += q4.z * k4.z; s[2][3] += q4.z * k4.w;
            s[3][0] += q4.w * k4.x; s[3][1] += q4.w * k4.y; s[3][2] += q4.w * k4.z; s[3][3] += q4.w * k4.w;
        }
#pragma unroll
        for (int i = 0; i < 4; i++) {
            float e0 = __expf(s[i][0]);
            float e1 = __expf(s[i][1]);
            float e2 = __expf(s[i][2]);
            float e3 = __expf(s[i][3]);
            lrun[i] += (e0 + e1) + (e2 + e3);
            uint4 pu;
            pu.x = f2tf32(e0); pu.y = f2tf32(e1);
            pu.z = f2tf32(e2); pu.w = f2tf32(e3);
            *(uint4*)&Pw[(rS + i) * TSTR + mS] = pu;
        }
    };

    // Prologue: K(0)->Kt0, sync, S(0)->Ps0, K(1)->Kt1, preload V block0, sync
    stage_k(gk_b, Kt0);
    __syncthreads();
    s_phase(Kt0, Ps0);
    stage_k(gk_b + KT * DQK, Kt1);

    float vcur[8];
#pragma unroll
    for (int jt = 0; jt < 4; jt++) {
        vcur[jt]     = gv_w[jt * 8];
        vcur[4 + jt] = gv_w[4 * CC + jt * 8];
    }
    __syncthreads();

    uint32_t* Pc = Ps0;  uint32_t* Pn = Ps1;
    float*    Kc = Kt1;  float*    Kw = Kt0;

    for (int kt = 0; kt < NKT; kt++) {
        const bool more = (kt + 1 < NKT);

        // K(kt+2): LDG now (latency hidden under PV), STS after PV
        float4 ka, kb;
        const bool dok = (kt + 2 < NKT);
        if (dok) {
            const float* gk_t = gk_b + (kt + 2) * KT * DQK;
            ka = *(const float4*)(gk_t + km0 * DQK + kd4);
            kb = *(const float4*)(gk_t + km1 * DQK + kd4);
        }

        // --- PV(kt): O += P V, V prefetch-pipelined from gmem ---
        {
            const float* vb = gv_w + (size_t)(kt * KT) * CC;
#pragma unroll
            for (int ks = 0; ks < 8; ks++) {
                float vnxt[8];
                if (ks < 7) {
                    const float* vn = vb + (ks + 1) * 8 * CC;
#pragma unroll
                    for (int jt = 0; jt < 4; jt++) {
                        vnxt[jt]     = vn[jt * 8];
                        vnxt[4 + jt] = vn[4 * CC + jt * 8];
                    }
                }
                uint32_t b0[4], b1[4];
#pragma unroll
                for (int jt = 0; jt < 4; jt++) {
                    b0[jt] = f2tf32(vcur[jt]);
                    b1[jt] = f2tf32(vcur[4 + jt]);
                }
                const int m0 = ks * 8;
#pragma unroll
                for (int it = 0; it < 4; it++) {
                    uint32_t a0 = Pc[(it * 16 + gid)     * TSTR + m0 + tid];
                    uint32_t a1 = Pc[(it * 16 + gid + 8) * TSTR + m0 + tid];
                    uint32_t a2 = Pc[(it * 16 + gid)     * TSTR + m0 + tid + 4];
                    uint32_t a3 = Pc[(it * 16 + gid + 8) * TSTR + m0 + tid + 4];
#pragma unroll
                    for (int jt = 0; jt < 4; jt++)
                        mma_tf32(acc[it][jt], a0, a1, a2, a3, b0[jt], b1[jt]);
                }
                if (ks < 7) {
#pragma unroll
                    for (int i = 0; i < 8; i++) vcur[i] = vnxt[i];
                }
            }
        }

        // Stage K(kt+2) into Kw (= Kt[kt%2]; no reader until after sync)
        if (dok) {
            Kw[(kd4 + 0) * TSTR + km0] = ka.x;
            Kw[(kd4 + 1) * TSTR + km0] = ka.y;
            Kw[(kd4 + 2) * TSTR + km0] = ka.z;
            Kw[(kd4 + 3) * TSTR + km0] = ka.w;
            Kw[(kd4 + 0) * TSTR + km1] = kb.x;
            Kw[(kd4 + 1) * TSTR + km1] = kb.y;
            Kw[(kd4 + 2) * TSTR + km1] = kb.z;
            Kw[(kd4 + 3) * TSTR + km1] = kb.w;
        }

        // --- S(kt+1) + exp + P store into Pn ---
        if (more) {
            s_phase(Kc, Pn);
            // preload V block0 of tile kt+1 (pure gmem read, pre-sync is safe)
            const float* vn = gv_w + (size_t)((kt + 1) * KT) * CC;
#pragma unroll
            for (int jt = 0; jt < 4; jt++) {
                vcur[jt]     = vn[jt * 8];
                vcur[4 + jt] = vn[4 * CC + jt * 8];
            }
        }
        __syncthreads();

        // swap buffers
        uint32_t* pt = Pc; Pc = Pn; Pn = pt;
        float*    ft = Kc; Kc = Kw; Kw = ft;
    }

    // --- final row-sum reduction ---
#pragma unroll
    for (int i = 0; i < 4; i++) {
        float l = lrun[i];
        l += __shfl_xor_sync(0xffffffffu, l, 1);
        l += __shfl_xor_sync(0xffffffffu, l, 2);
        l += __shfl_xor_sync(0xffffffffu, l, 4);
        l += __shfl_xor_sync(0xffffffffu, l, 8);
        if (txS == 0) inv_s[rS + i] = 1.f / l;
    }
    __syncthreads();

    // --- direct STG epilogue: out[b][c][n0+r] ---
    float* ob = out + (size_t)b * CC * NN + n0;
#pragma unroll
    for (int it = 0; it < 4; it++) {
        const int r_lo = it * 16 + gid;
        const int r_hi = r_lo + 8;
        const float ilo = inv_s[r_lo];
        const float ihi = inv_s[r_hi];
#pragma unroll
        for (int jt = 0; jt < 4; jt++) {
            const int c0 = cbase + jt * 8 + tid * 2;
            ob[(size_t)(c0    ) * NN + r_lo] = acc[it][jt][0] * ilo;
            ob[(size_t)(c0 + 1) * NN + r_lo] = acc[it][jt][1] * ilo;
            ob[(size_t)(c0    ) * NN + r_hi] = acc[it][jt][2] * ihi;
            ob[(size_t)(c0 + 1) * NN + r_hi] = acc[it][jt][3] * ihi;
        }
    }
}

// ---------------------------------------------------------------------------
extern "C" void kernel_launch(void* const* d_in, const int* in_sizes, int n_in,
                              void* d_out, int out_size)
{
    const float* f1 = (const float*)d_in[0];
    const float* f2 = (const float*)d_in[1];
    const float* Wq = (const float*)d_in[2];
    const float* bq = (const float*)d_in[3];
    const float* Wk = (const float*)d_in[4];
    const float* bk = (const float*)d_in[5];
    const float* Wv = (const float*)d_in[6];
    const float* bv = (const float*)d_in[7];
    float* out = (float*)d_out;

    float *qp, *kp, *vp;
    cudaGetSymbolAddress((void**)&qp, g_q);
    cudaGetSymbolAddress((void**)&kp, g_k);
    cudaGetSymbolAddress((void**)&vp, g_v);

    const int smem_bytes = SMEM_FLOATS * (int)sizeof(float);
    cudaFuncSetAttribute(flash_kernel,
                         cudaFuncAttributeMaxDynamicSharedMemorySize, smem_bytes);

    proj_kernel<<<dim3(NN / 128, 1, BB), 256>>>(f1, Wq, bq, qp, DQK);
    proj_kernel<<<dim3(NN / 128, 1, BB), 256>>>(f2, Wk, bk, kp, DQK);
    proj_kernel<<<dim3(NN / 128, 8, BB), 256>>>(f2, Wv, bv, vp, CC);
    flash_kernel<<<dim3(NN / 64, BB), 256, smem_bytes>>>(out);
}